// round 1
// baseline (speedup 1.0000x reference)
#include <cuda_runtime.h>
#include <math.h>

// ---------------- problem constants ----------------
#define BATCH   16
#define HW      112
#define CH      96
#define NHEADS  3
#define HD      32
#define WSZ     7
#define NTOK    49          // tokens per window
#define SHIFT_  3
#define NWIN    256         // windows per image (16x16)
#define TOTW    (BATCH*NWIN)        // 4096
#define MROWS   (TOTW*NTOK)         // 200704  (== BATCH * 112 * 112)
#define HIDDIM  384
#define LTOK    (HW*HW)             // 12544

// ---------------- scratch (no allocations allowed) ----------------
__device__ float g_xw  [MROWS*CH];        // LN1 output, window-ordered
__device__ float g_qkv [MROWS*3*CH];      // qkv, window-ordered
__device__ float g_att [MROWS*CH];        // attention out, window-ordered
__device__ float g_xmid[MROWS*CH];        // x + attn branch, image-ordered
__device__ float g_yln [MROWS*CH];        // LN2 output
__device__ float g_hid [MROWS*HIDDIM];    // fc1+gelu output
__device__ float g_wqkv[CH*3*CH];         // transposed weights (K-major)
__device__ float g_wproj[CH*CH];
__device__ float g_wfc1[CH*HIDDIM];
__device__ float g_wfc2[HIDDIM*CH];

// ---------------- weight transpose: W[N,K] -> Wt[K,N] ----------------
__global__ void transpose_w(const float* __restrict__ W, float* __restrict__ Wt,
                            int N, int K) {
    int idx = blockIdx.x * 256 + threadIdx.x;
    if (idx >= N * K) return;
    int n = idx / K, k = idx - n * K;
    Wt[k * N + n] = W[idx];
}

// ---------------- LN1 + cyclic shift + window partition ----------------
// One warp per output token (window-ordered row m). Gathers source pixel.
__global__ void ln1_gather(const float* __restrict__ x,
                           const float* __restrict__ gamma,
                           const float* __restrict__ beta) {
    int m    = blockIdx.x * 8 + (threadIdx.x >> 5);
    int lane = threadIdx.x & 31;
    int w = m / NTOK, t = m - w * NTOK;
    int bb = w >> 8;            // image
    int widx = w & 255;
    int wh = widx >> 4, wwi = widx & 15;
    int r = t / WSZ, cl = t - r * WSZ;
    int hh = (wh * WSZ + r  + SHIFT_) % HW;    // roll(-shift) gather
    int ww = (wwi * WSZ + cl + SHIFT_) % HW;
    const float* src = x + ((size_t)bb * LTOK + hh * HW + ww) * CH;
    float v0 = src[lane], v1 = src[lane + 32], v2 = src[lane + 64];
    float s  = v0 + v1 + v2;
    float ss = v0 * v0 + v1 * v1 + v2 * v2;
    #pragma unroll
    for (int o = 16; o > 0; o >>= 1) {
        s  += __shfl_xor_sync(~0u, s, o);
        ss += __shfl_xor_sync(~0u, ss, o);
    }
    float mean = s * (1.f / 96.f);
    float var  = ss * (1.f / 96.f) - mean * mean;
    float inv  = rsqrtf(var + 1e-5f);
    float* dst = g_xw + (size_t)m * CH;
    dst[lane]      = (v0 - mean) * inv * gamma[lane]      + beta[lane];
    dst[lane + 32] = (v1 - mean) * inv * gamma[lane + 32] + beta[lane + 32];
    dst[lane + 64] = (v2 - mean) * inv * gamma[lane + 64] + beta[lane + 64];
}

// ---------------- LN2 (image-ordered, no gather) ----------------
__global__ void ln2_kernel(const float* __restrict__ gamma,
                           const float* __restrict__ beta) {
    int m    = blockIdx.x * 8 + (threadIdx.x >> 5);
    int lane = threadIdx.x & 31;
    const float* src = g_xmid + (size_t)m * CH;
    float v0 = src[lane], v1 = src[lane + 32], v2 = src[lane + 64];
    float s  = v0 + v1 + v2;
    float ss = v0 * v0 + v1 * v1 + v2 * v2;
    #pragma unroll
    for (int o = 16; o > 0; o >>= 1) {
        s  += __shfl_xor_sync(~0u, s, o);
        ss += __shfl_xor_sync(~0u, ss, o);
    }
    float mean = s * (1.f / 96.f);
    float var  = ss * (1.f / 96.f) - mean * mean;
    float inv  = rsqrtf(var + 1e-5f);
    float* dst = g_yln + (size_t)m * CH;
    dst[lane]      = (v0 - mean) * inv * gamma[lane]      + beta[lane];
    dst[lane + 32] = (v1 - mean) * inv * gamma[lane + 32] + beta[lane + 32];
    dst[lane + 64] = (v2 - mean) * inv * gamma[lane + 64] + beta[lane + 64];
}

// ---------------- generic tiled GEMM: C[M,N] = A[M,K] @ Wt[K,N] + bias ----------------
// BM=64, BN=96, BK=32.  256 threads, 4x6 micro-tile each.
// EPI: 0 = store, 1 = GELU(exact)+store, 2 = +res store, 3 = window-reverse scatter + residual(x)
template<int EPI>
__global__ void gemm96(const float* __restrict__ A, const float* __restrict__ Bt,
                       const float* __restrict__ bias, float* __restrict__ Cout,
                       int Ncols, int K, const float* __restrict__ res) {
    __shared__ float As[32][64];
    __shared__ float Bs[32][96];
    int tid = threadIdx.x;
    int rowBase = blockIdx.y * 64;
    int colBase = blockIdx.x * 96;
    int tm = tid >> 4, tn = tid & 15;
    float acc[4][6];
    #pragma unroll
    for (int i = 0; i < 4; i++)
        #pragma unroll
        for (int j = 0; j < 6; j++) acc[i][j] = 0.f;
    int am = tid >> 2;
    int ak = (tid & 3) * 8;

    for (int k0 = 0; k0 < K; k0 += 32) {
        const float* ap = A + (size_t)(rowBase + am) * K + k0 + ak;
        float4 a0 = *(const float4*)ap;
        float4 a1 = *(const float4*)(ap + 4);
        As[ak + 0][am] = a0.x; As[ak + 1][am] = a0.y;
        As[ak + 2][am] = a0.z; As[ak + 3][am] = a0.w;
        As[ak + 4][am] = a1.x; As[ak + 5][am] = a1.y;
        As[ak + 6][am] = a1.z; As[ak + 7][am] = a1.w;
        #pragma unroll
        for (int idx = tid; idx < 32 * 96; idx += 256) {
            int bk = idx / 96, bn = idx - bk * 96;
            Bs[bk][bn] = Bt[(size_t)(k0 + bk) * Ncols + colBase + bn];
        }
        __syncthreads();
        #pragma unroll
        for (int kk = 0; kk < 32; kk++) {
            float4 a = *(const float4*)&As[kk][tm * 4];
            const float* bp = &Bs[kk][tn * 6];
            #pragma unroll
            for (int j = 0; j < 6; j++) {
                float bv = bp[j];
                acc[0][j] += a.x * bv; acc[1][j] += a.y * bv;
                acc[2][j] += a.z * bv; acc[3][j] += a.w * bv;
            }
        }
        __syncthreads();
    }

    #pragma unroll
    for (int i = 0; i < 4; i++) {
        int row = rowBase + tm * 4 + i;
        if (EPI == 3) {
            // window reverse + reverse shift + residual from original x
            int w = row / NTOK, t = row - w * NTOK;
            int bb = w >> 8;
            int widx = w & 255;
            int wh = widx >> 4, wwi = widx & 15;
            int r = t / WSZ, cl = t - r * WSZ;
            int hu = (wh * WSZ + r  + SHIFT_) % HW;
            int wu = (wwi * WSZ + cl + SHIFT_) % HW;
            size_t orow = (size_t)bb * LTOK + hu * HW + wu;
            #pragma unroll
            for (int j = 0; j < 6; j++) {
                int col = colBase + tn * 6 + j;
                float v = acc[i][j] + bias[col];
                v += res[orow * CH + col];
                Cout[orow * CH + col] = v;
            }
        } else {
            size_t base = (size_t)row * Ncols + colBase + tn * 6;
            #pragma unroll
            for (int j = 0; j < 6; j++) {
                int col = colBase + tn * 6 + j;
                float v = acc[i][j] + bias[col];
                if (EPI == 1) v = 0.5f * v * (1.f + erff(v * 0.70710678118654752f));
                if (EPI == 2) v += res[base + j];
                Cout[base + j] = v;
            }
        }
    }
}

// ---------------- attention: one block per (window, head) ----------------
__global__ void attn_kernel(const float* __restrict__ mask,
                            const float* __restrict__ relt) {
    int w = blockIdx.x / NHEADS;
    int h = blockIdx.x - w * NHEADS;
    __shared__ float qs[NTOK * HD];
    __shared__ float ks[NTOK * 33];
    __shared__ float vs[NTOK * 33];
    __shared__ float sc[NTOK * 52];
    int tid = threadIdx.x;
    const float scale = 0.17677669529663687f;  // 1/sqrt(32)
    const float* base = g_qkv + (size_t)w * NTOK * (3 * CH);

    for (int idx = tid; idx < NTOK * HD; idx += 256) {
        int t = idx >> 5, d = idx & 31;
        const float* p = base + t * (3 * CH) + h * HD + d;
        qs[idx]        = p[0] * scale;
        ks[t * 33 + d] = p[CH];
        vs[t * 33 + d] = p[2 * CH];
    }
    __syncthreads();

    const float* mk = mask + (size_t)(w & 255) * NTOK * NTOK;
    for (int p = tid; p < NTOK * NTOK; p += 256) {
        int i = p / NTOK, j = p - i * NTOK;
        const float* qp = qs + i * HD;
        const float* kp = ks + j * 33;
        float s = 0.f;
        #pragma unroll
        for (int d = 0; d < HD; d++) s += qp[d] * kp[d];
        int ri = i / 7, ci = i - ri * 7;
        int rj = j / 7, cj = j - rj * 7;
        int bidx = (ri - rj + 6) * 13 + (ci - cj + 6);
        s += relt[bidx * NHEADS + h] + mk[p];
        sc[i * 52 + j] = s;
    }
    __syncthreads();

    if (tid < NTOK) {
        float* row = sc + tid * 52;
        float mx = -1e30f;
        for (int j = 0; j < NTOK; j++) mx = fmaxf(mx, row[j]);
        float sum = 0.f;
        for (int j = 0; j < NTOK; j++) { float e = __expf(row[j] - mx); row[j] = e; sum += e; }
        float inv = 1.f / sum;
        for (int j = 0; j < NTOK; j++) row[j] *= inv;
    }
    __syncthreads();

    for (int p = tid; p < NTOK * HD; p += 256) {
        int i = p >> 5, d = p & 31;
        const float* sp = sc + i * 52;
        float acc = 0.f;
        #pragma unroll 7
        for (int j = 0; j < NTOK; j++) acc += sp[j] * vs[j * 33 + d];
        g_att[(size_t)(w * NTOK + i) * CH + h * HD + d] = acc;
    }
}

// ---------------- launch ----------------
extern "C" void kernel_launch(void* const* d_in, const int* in_sizes, int n_in,
                              void* d_out, int out_size) {
    const float* x     = (const float*)d_in[0];
    const float* mask  = (const float*)d_in[1];
    const float* n1g   = (const float*)d_in[2];
    const float* n1b   = (const float*)d_in[3];
    const float* qkvw  = (const float*)d_in[4];
    const float* qkvb  = (const float*)d_in[5];
    const float* relt  = (const float*)d_in[6];
    const float* projw = (const float*)d_in[7];
    const float* projb = (const float*)d_in[8];
    const float* n2g   = (const float*)d_in[9];
    const float* n2b   = (const float*)d_in[10];
    const float* fc1w  = (const float*)d_in[11];
    const float* fc1b  = (const float*)d_in[12];
    const float* fc2w  = (const float*)d_in[13];
    const float* fc2b  = (const float*)d_in[14];
    float* out = (float*)d_out;

    float *p_xw, *p_qkv, *p_att, *p_xmid, *p_yln, *p_hid;
    float *p_wqkv, *p_wproj, *p_wfc1, *p_wfc2;
    cudaGetSymbolAddress((void**)&p_xw,   g_xw);
    cudaGetSymbolAddress((void**)&p_qkv,  g_qkv);
    cudaGetSymbolAddress((void**)&p_att,  g_att);
    cudaGetSymbolAddress((void**)&p_xmid, g_xmid);
    cudaGetSymbolAddress((void**)&p_yln,  g_yln);
    cudaGetSymbolAddress((void**)&p_hid,  g_hid);
    cudaGetSymbolAddress((void**)&p_wqkv, g_wqkv);
    cudaGetSymbolAddress((void**)&p_wproj,g_wproj);
    cudaGetSymbolAddress((void**)&p_wfc1, g_wfc1);
    cudaGetSymbolAddress((void**)&p_wfc2, g_wfc2);

    // 1) transpose weights to K-major (tiny; keeps GEMM B-loads coalesced)
    transpose_w<<<(3*CH*CH + 255)/256, 256>>>(qkvw, p_wqkv, 3*CH, CH);
    transpose_w<<<(CH*CH   + 255)/256, 256>>>(projw, p_wproj, CH, CH);
    transpose_w<<<(HIDDIM*CH + 255)/256, 256>>>(fc1w, p_wfc1, HIDDIM, CH);
    transpose_w<<<(CH*HIDDIM + 255)/256, 256>>>(fc2w, p_wfc2, CH, HIDDIM);

    // 2) LN1 + shift + window partition
    ln1_gather<<<MROWS/8, 256>>>(x, n1g, n1b);

    // 3) QKV GEMM  (M x 288, K=96)
    gemm96<0><<<dim3(3, MROWS/64), 256>>>(p_xw, p_wqkv, qkvb, p_qkv, 3*CH, CH, nullptr);

    // 4) windowed attention
    attn_kernel<<<TOTW * NHEADS, 256>>>(mask, relt);

    // 5) proj GEMM + window reverse + unshift + residual (reads original x)
    gemm96<3><<<dim3(1, MROWS/64), 256>>>(p_att, p_wproj, projb, p_xmid, CH, CH, x);

    // 6) LN2
    ln2_kernel<<<MROWS/8, 256>>>(n2g, n2b);

    // 7) fc1 + exact GELU  (M x 384, K=96)
    gemm96<1><<<dim3(4, MROWS/64), 256>>>(p_yln, p_wfc1, fc1b, p_hid, HIDDIM, CH, nullptr);

    // 8) fc2 + residual -> out  (M x 96, K=384)
    gemm96<2><<<dim3(1, MROWS/64), 256>>>(p_hid, p_wfc2, fc2b, out, CH, HIDDIM, p_xmid);
}

// round 2
// speedup vs baseline: 1.6798x; 1.6798x over previous
#include <cuda_runtime.h>
#include <math.h>
#include <stdint.h>

// ---------------- problem constants ----------------
#define BATCH   16
#define HW      112
#define CH      96
#define NHEADS  3
#define HD      32
#define WSZ     7
#define NTOK    49
#define SHIFT_  3
#define NWIN    256
#define TOTW    (BATCH*NWIN)        // 4096
#define MROWS   (TOTW*NTOK)         // 200704
#define HIDDIM  384
#define LTOK    (HW*HW)             // 12544

// GEMM tile
#define BM 128
#define BN 96
#define BK 32

// ---------------- scratch ----------------
__device__ float g_xw  [MROWS*CH];
__device__ float g_qkv [MROWS*3*CH];
__device__ float g_att [MROWS*CH];
__device__ float g_xmid[MROWS*CH];
__device__ float g_yln [MROWS*CH];
__device__ float g_hid [MROWS*HIDDIM];
__device__ float g_wqkv[CH*3*CH];
__device__ float g_wproj[CH*CH];
__device__ float g_wfc1[CH*HIDDIM];
__device__ float g_wfc2[HIDDIM*CH];

// ---------------- helpers ----------------
__device__ __forceinline__ float f2tf(float x) {
    uint32_t r;
    asm("cvt.rna.tf32.f32 %0, %1;" : "=r"(r) : "f"(x));
    return __uint_as_float(r);
}

__device__ __forceinline__ void mma_tf32(float* c, const uint32_t* a, const uint32_t* b) {
    asm volatile(
        "mma.sync.aligned.m16n8k8.row.col.f32.tf32.tf32.f32 "
        "{%0,%1,%2,%3}, {%4,%5,%6,%7}, {%8,%9}, {%0,%1,%2,%3};\n"
        : "+f"(c[0]), "+f"(c[1]), "+f"(c[2]), "+f"(c[3])
        : "r"(a[0]), "r"(a[1]), "r"(a[2]), "r"(a[3]), "r"(b[0]), "r"(b[1]));
}

// ---------------- weight transpose: W[N,K] -> Wt[K,N] ----------------
__global__ void transpose_w(const float* __restrict__ W, float* __restrict__ Wt,
                            int N, int K) {
    int idx = blockIdx.x * 256 + threadIdx.x;
    if (idx >= N * K) return;
    int n = idx / K, k = idx - n * K;
    Wt[k * N + n] = W[idx];
}

// ---------------- LN1 + cyclic shift + window partition ----------------
__global__ void ln1_gather(const float* __restrict__ x,
                           const float* __restrict__ gamma,
                           const float* __restrict__ beta) {
    int m    = blockIdx.x * 8 + (threadIdx.x >> 5);
    int lane = threadIdx.x & 31;
    int w = m / NTOK, t = m - w * NTOK;
    int bb = w >> 8;
    int widx = w & 255;
    int wh = widx >> 4, wwi = widx & 15;
    int r = t / WSZ, cl = t - r * WSZ;
    int hh = (wh * WSZ + r  + SHIFT_) % HW;
    int ww = (wwi * WSZ + cl + SHIFT_) % HW;
    const float* src = x + ((size_t)bb * LTOK + hh * HW + ww) * CH;
    float v0 = src[lane], v1 = src[lane + 32], v2 = src[lane + 64];
    float s  = v0 + v1 + v2;
    float ss = v0 * v0 + v1 * v1 + v2 * v2;
    #pragma unroll
    for (int o = 16; o > 0; o >>= 1) {
        s  += __shfl_xor_sync(~0u, s, o);
        ss += __shfl_xor_sync(~0u, ss, o);
    }
    float mean = s * (1.f / 96.f);
    float var  = ss * (1.f / 96.f) - mean * mean;
    float inv  = rsqrtf(var + 1e-5f);
    float* dst = g_xw + (size_t)m * CH;
    dst[lane]      = (v0 - mean) * inv * gamma[lane]      + beta[lane];
    dst[lane + 32] = (v1 - mean) * inv * gamma[lane + 32] + beta[lane + 32];
    dst[lane + 64] = (v2 - mean) * inv * gamma[lane + 64] + beta[lane + 64];
}

// ---------------- LN2 ----------------
__global__ void ln2_kernel(const float* __restrict__ gamma,
                           const float* __restrict__ beta) {
    int m    = blockIdx.x * 8 + (threadIdx.x >> 5);
    int lane = threadIdx.x & 31;
    const float* src = g_xmid + (size_t)m * CH;
    float v0 = src[lane], v1 = src[lane + 32], v2 = src[lane + 64];
    float s  = v0 + v1 + v2;
    float ss = v0 * v0 + v1 * v1 + v2 * v2;
    #pragma unroll
    for (int o = 16; o > 0; o >>= 1) {
        s  += __shfl_xor_sync(~0u, s, o);
        ss += __shfl_xor_sync(~0u, ss, o);
    }
    float mean = s * (1.f / 96.f);
    float var  = ss * (1.f / 96.f) - mean * mean;
    float inv  = rsqrtf(var + 1e-5f);
    float* dst = g_yln + (size_t)m * CH;
    dst[lane]      = (v0 - mean) * inv * gamma[lane]      + beta[lane];
    dst[lane + 32] = (v1 - mean) * inv * gamma[lane + 32] + beta[lane + 32];
    dst[lane + 64] = (v2 - mean) * inv * gamma[lane + 64] + beta[lane + 64];
}

// ---------------- tensor-core GEMM: C[M,N] = A[M,K] @ Wt[K,N] + bias ----------------
// BM=128, BN=96, BK=32. 256 threads (8 warps), warp tile 32x48 via m16n8k8 tf32.
// EPI: 0 = store, 1 = exact GELU, 2 = +res, 3 = window-reverse scatter + residual(x)
template<int EPI>
__global__ void __launch_bounds__(256)
gemm_tc(const float* __restrict__ A, const float* __restrict__ Bt,
        const float* __restrict__ bias, float* __restrict__ Cout,
        int Ncols, int K, const float* __restrict__ res) {
    __shared__ float As[BK][BM + 8];   // stride 136: 8r+c banks -> conflict-free frags
    __shared__ float Bs[BK][BN + 8];   // stride 104: same property

    int tid  = threadIdx.x;
    int warp = tid >> 5, lane = tid & 31;
    int g = lane >> 2, tg = lane & 3;
    int wm = (warp >> 1) * 32;
    int wn = (warp & 1) * 48;
    int rowBase = blockIdx.y * BM;
    int colBase = blockIdx.x * BN;

    float c[2][6][4];
    #pragma unroll
    for (int mt = 0; mt < 2; mt++)
        #pragma unroll
        for (int j = 0; j < 6; j++)
            #pragma unroll
            for (int q = 0; q < 4; q++) c[mt][j][q] = 0.f;

    int am  = tid >> 1;        // 0..127
    int akq = (tid & 1) * 16;  // 0 / 16

    for (int k0 = 0; k0 < K; k0 += BK) {
        // A tile -> transposed [k][m], converted to tf32 bits
        const float* ap = A + (size_t)(rowBase + am) * K + k0 + akq;
        #pragma unroll
        for (int i = 0; i < 4; i++) {
            float4 v = *(const float4*)(ap + 4 * i);
            As[akq + 4*i + 0][am] = f2tf(v.x);
            As[akq + 4*i + 1][am] = f2tf(v.y);
            As[akq + 4*i + 2][am] = f2tf(v.z);
            As[akq + 4*i + 3][am] = f2tf(v.w);
        }
        // B tile [k][n]
        #pragma unroll
        for (int i = 0; i < 3; i++) {
            int lin = tid + 256 * i;            // float4 units, 768 total
            int bk = lin / 24, bn4 = (lin - bk * 24) * 4;
            float4 v = *(const float4*)(Bt + (size_t)(k0 + bk) * Ncols + colBase + bn4);
            float4 w = make_float4(f2tf(v.x), f2tf(v.y), f2tf(v.z), f2tf(v.w));
            *(float4*)&Bs[bk][bn4] = w;
        }
        __syncthreads();

        #pragma unroll
        for (int kk = 0; kk < BK; kk += 8) {
            uint32_t a[2][4], b[6][2];
            #pragma unroll
            for (int mt = 0; mt < 2; mt++) {
                int m0 = wm + mt * 16;
                a[mt][0] = __float_as_uint(As[kk + tg    ][m0 + g    ]);
                a[mt][1] = __float_as_uint(As[kk + tg    ][m0 + g + 8]);
                a[mt][2] = __float_as_uint(As[kk + tg + 4][m0 + g    ]);
                a[mt][3] = __float_as_uint(As[kk + tg + 4][m0 + g + 8]);
            }
            #pragma unroll
            for (int j = 0; j < 6; j++) {
                int n0 = wn + 8 * j;
                b[j][0] = __float_as_uint(Bs[kk + tg    ][n0 + g]);
                b[j][1] = __float_as_uint(Bs[kk + tg + 4][n0 + g]);
            }
            #pragma unroll
            for (int mt = 0; mt < 2; mt++)
                #pragma unroll
                for (int j = 0; j < 6; j++)
                    mma_tf32(c[mt][j], a[mt], b[j]);
        }
        __syncthreads();
    }

    // epilogue: thread owns rows {wm+mt*16+g, +8}, cols {wn+8j+2tg, +1}
    #pragma unroll
    for (int mt = 0; mt < 2; mt++) {
        #pragma unroll
        for (int rr = 0; rr < 2; rr++) {
            int row = rowBase + wm + mt * 16 + g + rr * 8;
            if (EPI == 3) {
                int w = row / NTOK, t = row - w * NTOK;
                int bb = w >> 8;
                int widx = w & 255;
                int wh = widx >> 4, wwi = widx & 15;
                int r = t / WSZ, cl = t - r * WSZ;
                int hu = (wh * WSZ + r  + SHIFT_) % HW;
                int wu = (wwi * WSZ + cl + SHIFT_) % HW;
                size_t orow = ((size_t)bb * LTOK + hu * HW + wu) * CH;
                #pragma unroll
                for (int j = 0; j < 6; j++) {
                    #pragma unroll
                    for (int cc = 0; cc < 2; cc++) {
                        int col = colBase + wn + 8 * j + 2 * tg + cc;
                        float v = c[mt][j][rr * 2 + cc] + bias[col];
                        Cout[orow + col] = v + res[orow + col];
                    }
                }
            } else {
                size_t base = (size_t)row * Ncols;
                #pragma unroll
                for (int j = 0; j < 6; j++) {
                    #pragma unroll
                    for (int cc = 0; cc < 2; cc++) {
                        int col = colBase + wn + 8 * j + 2 * tg + cc;
                        float v = c[mt][j][rr * 2 + cc] + bias[col];
                        if (EPI == 1) v = 0.5f * v * (1.f + erff(v * 0.70710678118654752f));
                        if (EPI == 2) v += res[base + col];
                        Cout[base + col] = v;
                    }
                }
            }
        }
    }
}

// ---------------- attention: one block per (window, head) ----------------
__global__ void attn_kernel(const float* __restrict__ mask,
                            const float* __restrict__ relt) {
    int w = blockIdx.x / NHEADS;
    int h = blockIdx.x - w * NHEADS;
    __shared__ float qs[NTOK * HD];
    __shared__ float ks[NTOK * 33];
    __shared__ float vs[NTOK * 33];
    __shared__ float sc[NTOK * 52];
    int tid = threadIdx.x;
    const float scale = 0.17677669529663687f;
    const float* base = g_qkv + (size_t)w * NTOK * (3 * CH);

    for (int idx = tid; idx < NTOK * HD; idx += 256) {
        int t = idx >> 5, d = idx & 31;
        const float* p = base + t * (3 * CH) + h * HD + d;
        qs[idx]        = p[0] * scale;
        ks[t * 33 + d] = p[CH];
        vs[t * 33 + d] = p[2 * CH];
    }
    __syncthreads();

    const float* mk = mask + (size_t)(w & 255) * NTOK * NTOK;
    for (int p = tid; p < NTOK * NTOK; p += 256) {
        int i = p / NTOK, j = p - i * NTOK;
        const float* qp = qs + i * HD;
        const float* kp = ks + j * 33;
        float s = 0.f;
        #pragma unroll
        for (int d = 0; d < HD; d++) s += qp[d] * kp[d];
        int ri = i / 7, ci = i - ri * 7;
        int rj = j / 7, cj = j - rj * 7;
        int bidx = (ri - rj + 6) * 13 + (ci - cj + 6);
        s += relt[bidx * NHEADS + h] + mk[p];
        sc[i * 52 + j] = s;
    }
    __syncthreads();

    if (tid < NTOK) {
        float* row = sc + tid * 52;
        float mx = -1e30f;
        for (int j = 0; j < NTOK; j++) mx = fmaxf(mx, row[j]);
        float sum = 0.f;
        for (int j = 0; j < NTOK; j++) { float e = __expf(row[j] - mx); row[j] = e; sum += e; }
        float inv = 1.f / sum;
        for (int j = 0; j < NTOK; j++) row[j] *= inv;
    }
    __syncthreads();

    for (int p = tid; p < NTOK * HD; p += 256) {
        int i = p >> 5, d = p & 31;
        const float* sp = sc + i * 52;
        float acc = 0.f;
        #pragma unroll 7
        for (int j = 0; j < NTOK; j++) acc += sp[j] * vs[j * 33 + d];
        g_att[(size_t)(w * NTOK + i) * CH + h * HD + d] = acc;
    }
}

// ---------------- launch ----------------
extern "C" void kernel_launch(void* const* d_in, const int* in_sizes, int n_in,
                              void* d_out, int out_size) {
    const float* x     = (const float*)d_in[0];
    const float* mask  = (const float*)d_in[1];
    const float* n1g   = (const float*)d_in[2];
    const float* n1b   = (const float*)d_in[3];
    const float* qkvw  = (const float*)d_in[4];
    const float* qkvb  = (const float*)d_in[5];
    const float* relt  = (const float*)d_in[6];
    const float* projw = (const float*)d_in[7];
    const float* projb = (const float*)d_in[8];
    const float* n2g   = (const float*)d_in[9];
    const float* n2b   = (const float*)d_in[10];
    const float* fc1w  = (const float*)d_in[11];
    const float* fc1b  = (const float*)d_in[12];
    const float* fc2w  = (const float*)d_in[13];
    const float* fc2b  = (const float*)d_in[14];
    float* out = (float*)d_out;

    float *p_xw, *p_qkv, *p_att, *p_xmid, *p_yln, *p_hid;
    float *p_wqkv, *p_wproj, *p_wfc1, *p_wfc2;
    cudaGetSymbolAddress((void**)&p_xw,   g_xw);
    cudaGetSymbolAddress((void**)&p_qkv,  g_qkv);
    cudaGetSymbolAddress((void**)&p_att,  g_att);
    cudaGetSymbolAddress((void**)&p_xmid, g_xmid);
    cudaGetSymbolAddress((void**)&p_yln,  g_yln);
    cudaGetSymbolAddress((void**)&p_hid,  g_hid);
    cudaGetSymbolAddress((void**)&p_wqkv, g_wqkv);
    cudaGetSymbolAddress((void**)&p_wproj,g_wproj);
    cudaGetSymbolAddress((void**)&p_wfc1, g_wfc1);
    cudaGetSymbolAddress((void**)&p_wfc2, g_wfc2);

    transpose_w<<<(3*CH*CH + 255)/256, 256>>>(qkvw, p_wqkv, 3*CH, CH);
    transpose_w<<<(CH*CH   + 255)/256, 256>>>(projw, p_wproj, CH, CH);
    transpose_w<<<(HIDDIM*CH + 255)/256, 256>>>(fc1w, p_wfc1, HIDDIM, CH);
    transpose_w<<<(CH*HIDDIM + 255)/256, 256>>>(fc2w, p_wfc2, CH, HIDDIM);

    ln1_gather<<<MROWS/8, 256>>>(x, n1g, n1b);

    // QKV: M x 288, K = 96
    gemm_tc<0><<<dim3(3, MROWS/BM), 256>>>(p_xw, p_wqkv, qkvb, p_qkv, 3*CH, CH, nullptr);

    attn_kernel<<<TOTW * NHEADS, 256>>>(mask, relt);

    // proj + window reverse + unshift + residual(x)
    gemm_tc<3><<<dim3(1, MROWS/BM), 256>>>(p_att, p_wproj, projb, p_xmid, CH, CH, x);

    ln2_kernel<<<MROWS/8, 256>>>(n2g, n2b);

    // fc1 + GELU: M x 384, K = 96
    gemm_tc<1><<<dim3(4, MROWS/BM), 256>>>(p_yln, p_wfc1, fc1b, p_hid, HIDDIM, CH, nullptr);

    // fc2 + residual: M x 96, K = 384
    gemm_tc<2><<<dim3(1, MROWS/BM), 256>>>(p_hid, p_wfc2, fc2b, out, CH, HIDDIM, p_xmid);
}

// round 5
// speedup vs baseline: 2.3097x; 1.3750x over previous
#include <cuda_runtime.h>
#include <cuda_bf16.h>
#include <math.h>
#include <stdint.h>

// ---------------- problem constants ----------------
#define BATCH   16
#define HW      112
#define CH      96
#define NHEADS  3
#define HD      32
#define WSZ     7
#define NTOK    49
#define SHIFT_  3
#define TOTW    4096
#define MROWS   200704
#define HIDDIM  384
#define LTOK    12544

// ---------------- scratch ----------------
__device__ __align__(256) __nv_bfloat16 g_xw  [MROWS*CH];
__device__ __align__(256) __nv_bfloat16 g_qkv [MROWS*3*CH];
__device__ __align__(256) __nv_bfloat16 g_att [MROWS*CH];
__device__ __align__(256) float         g_xmid[MROWS*CH];
__device__ uint32_t g_wqkvp[48*288];   // bf16-pair [K/2][N]
__device__ uint32_t g_wprojp[48*96];
__device__ uint32_t g_wfc1p[48*384];
__device__ uint32_t g_wfc2p[192*96];

// ---------------- helpers ----------------
__device__ __forceinline__ uint32_t pack_bf(float lo, float hi) {
    unsigned short l = __bfloat16_as_ushort(__float2bfloat16_rn(lo));
    unsigned short h = __bfloat16_as_ushort(__float2bfloat16_rn(hi));
    return ((uint32_t)h << 16) | (uint32_t)l;
}

__device__ __forceinline__ void mma_bf16(float* c, const uint32_t* a, const uint32_t* b) {
    asm volatile(
        "mma.sync.aligned.m16n8k16.row.col.f32.bf16.bf16.f32 "
        "{%0,%1,%2,%3}, {%4,%5,%6,%7}, {%8,%9}, {%0,%1,%2,%3};\n"
        : "+f"(c[0]), "+f"(c[1]), "+f"(c[2]), "+f"(c[3])
        : "r"(a[0]), "r"(a[1]), "r"(a[2]), "r"(a[3]), "r"(b[0]), "r"(b[1]));
}

// one K=96 warp-tile GEMM: A pairs [48][136], B pairs [48][104]; warp tile 32x48
__device__ __forceinline__ void gemm_frag_96(const uint32_t (*Ap)[136],
                                             const uint32_t (*Bw)[104],
                                             int wm, int wn, int g, int tg,
                                             float c[2][6][4]) {
    #pragma unroll
    for (int ks = 0; ks < 6; ks++) {
        int kp0 = ks * 8;
        uint32_t a[2][4], b[6][2];
        #pragma unroll
        for (int mt = 0; mt < 2; mt++) {
            int m0 = wm + mt * 16;
            a[mt][0] = Ap[kp0 + tg    ][m0 + g];
            a[mt][1] = Ap[kp0 + tg    ][m0 + g + 8];
            a[mt][2] = Ap[kp0 + tg + 4][m0 + g];
            a[mt][3] = Ap[kp0 + tg + 4][m0 + g + 8];
        }
        #pragma unroll
        for (int j = 0; j < 6; j++) {
            int n0 = wn + 8 * j;
            b[j][0] = Bw[kp0 + tg    ][n0 + g];
            b[j][1] = Bw[kp0 + tg + 4][n0 + g];
        }
        #pragma unroll
        for (int mt = 0; mt < 2; mt++)
            #pragma unroll
            for (int j = 0; j < 6; j++)
                mma_bf16(c[mt][j], a[mt], b[j]);
    }
}

// ---------------- weight prep: fp32 W[N,K] -> bf16 pair Wt[K/2][N] ----------------
__global__ void prep_weights(const float* __restrict__ qkvw, const float* __restrict__ projw,
                             const float* __restrict__ fc1w, const float* __restrict__ fc2w) {
    int idx = blockIdx.x * 256 + threadIdx.x;
    if (idx < 13824) {                       // qkv: K=96, N=288
        int kp = idx / 288, n = idx - kp * 288;
        g_wqkvp[idx] = pack_bf(qkvw[n * 96 + 2 * kp], qkvw[n * 96 + 2 * kp + 1]);
    } else if (idx < 13824 + 4608) {          // proj: K=96, N=96
        int i = idx - 13824;
        int kp = i / 96, n = i - kp * 96;
        g_wprojp[i] = pack_bf(projw[n * 96 + 2 * kp], projw[n * 96 + 2 * kp + 1]);
    } else if (idx < 13824 + 4608 + 18432) {  // fc1: K=96, N=384
        int i = idx - 13824 - 4608;
        int kp = i / 384, n = i - kp * 384;
        g_wfc1p[i] = pack_bf(fc1w[n * 96 + 2 * kp], fc1w[n * 96 + 2 * kp + 1]);
    } else if (idx < 55296) {                 // fc2: K=384, N=96
        int i = idx - 13824 - 4608 - 18432;
        int kp = i / 96, n = i - kp * 96;
        g_wfc2p[i] = pack_bf(fc2w[n * 384 + 2 * kp], fc2w[n * 384 + 2 * kp + 1]);
    }
}

// ---------------- LN1 + cyclic shift + window partition (bf16 out) ----------------
__global__ void ln1_gather(const float* __restrict__ x,
                           const float* __restrict__ gamma,
                           const float* __restrict__ beta) {
    int m    = blockIdx.x * 8 + (threadIdx.x >> 5);
    int lane = threadIdx.x & 31;
    int w = m / NTOK, t = m - w * NTOK;
    int bb = w >> 8;
    int widx = w & 255;
    int wh = widx >> 4, wwi = widx & 15;
    int r = t / WSZ, cl = t - r * WSZ;
    int hh = (wh * WSZ + r  + SHIFT_) % HW;
    int ww = (wwi * WSZ + cl + SHIFT_) % HW;
    const float* src = x + ((size_t)bb * LTOK + hh * HW + ww) * CH;
    float v0 = src[lane], v1 = src[lane + 32], v2 = src[lane + 64];
    float s  = v0 + v1 + v2;
    float ss = v0 * v0 + v1 * v1 + v2 * v2;
    #pragma unroll
    for (int o = 16; o > 0; o >>= 1) {
        s  += __shfl_xor_sync(~0u, s, o);
        ss += __shfl_xor_sync(~0u, ss, o);
    }
    float mean = s * (1.f / 96.f);
    float var  = ss * (1.f / 96.f) - mean * mean;
    float inv  = rsqrtf(var + 1e-5f);
    __nv_bfloat16* dst = g_xw + (size_t)m * CH;
    dst[lane]      = __float2bfloat16_rn((v0 - mean) * inv * gamma[lane]      + beta[lane]);
    dst[lane + 32] = __float2bfloat16_rn((v1 - mean) * inv * gamma[lane + 32] + beta[lane + 32]);
    dst[lane + 64] = __float2bfloat16_rn((v2 - mean) * inv * gamma[lane + 64] + beta[lane + 64]);
}

// ---------------- bf16 tensor-core GEMM, K=96 fixed, BM=128, BN=96 ----------------
// EPI 0: bf16 pair store (+bias)  [qkv]
// EPI 3: fp32 window-reverse scatter + residual(x)  [proj]
template<int EPI>
__global__ void __launch_bounds__(256)
gemm_bf16(const __nv_bfloat16* __restrict__ A, const uint32_t* __restrict__ Bp,
          const float* __restrict__ bias, void* __restrict__ CoutV,
          int Ncols, const float* __restrict__ res) {
    __shared__ uint32_t As[48][136];
    __shared__ uint32_t Bs[48][104];
    int tid = threadIdx.x;
    int warp = tid >> 5, lane = tid & 31;
    int g = lane >> 2, tg = lane & 3;
    int wm = (warp >> 1) * 32, wn = (warp & 1) * 48;
    int rowBase = blockIdx.y * 128, colBase = blockIdx.x * 96;

    {   // A tile: 128 rows x 48 pairs
        int row = tid >> 1, half = tid & 1;
        const uint4* ap = (const uint4*)(A + (size_t)(rowBase + row) * 96 + half * 48);
        #pragma unroll
        for (int i = 0; i < 6; i++) {
            uint4 v = ap[i];
            int kp = half * 24 + 4 * i;
            As[kp][row] = v.x; As[kp + 1][row] = v.y;
            As[kp + 2][row] = v.z; As[kp + 3][row] = v.w;
        }
    }
    #pragma unroll
    for (int i = 0; i < 18; i++) {   // B tile: 48 x 96 pairs
        int idx = tid + 256 * i;
        int kp = idx / 96, n = idx - kp * 96;
        Bs[kp][n] = Bp[(size_t)kp * Ncols + colBase + n];
    }
    __syncthreads();

    float c[2][6][4];
    #pragma unroll
    for (int mt = 0; mt < 2; mt++)
        #pragma unroll
        for (int j = 0; j < 6; j++)
            #pragma unroll
            for (int q = 0; q < 4; q++) c[mt][j][q] = 0.f;

    gemm_frag_96(As, Bs, wm, wn, g, tg, c);

    #pragma unroll
    for (int mt = 0; mt < 2; mt++) {
        #pragma unroll
        for (int rr = 0; rr < 2; rr++) {
            int row = rowBase + wm + mt * 16 + g + rr * 8;
            if (EPI == 3) {
                int w = row / NTOK, t = row - w * NTOK;
                int bb = w >> 8;
                int widx = w & 255;
                int wh = widx >> 4, wwi = widx & 15;
                int r = t / WSZ, cl = t - r * WSZ;
                int hu = (wh * WSZ + r  + SHIFT_) % HW;
                int wu = (wwi * WSZ + cl + SHIFT_) % HW;
                size_t orow = ((size_t)bb * LTOK + hu * HW + wu) * CH;
                float* O = (float*)CoutV;
                #pragma unroll
                for (int j = 0; j < 6; j++) {
                    int col = colBase + wn + 8 * j + 2 * tg;
                    O[orow + col]     = c[mt][j][rr * 2]     + bias[col]     + res[orow + col];
                    O[orow + col + 1] = c[mt][j][rr * 2 + 1] + bias[col + 1] + res[orow + col + 1];
                }
            } else {
                uint32_t* O32 = (uint32_t*)CoutV;
                #pragma unroll
                for (int j = 0; j < 6; j++) {
                    int col = colBase + wn + 8 * j + 2 * tg;
                    float v0 = c[mt][j][rr * 2]     + bias[col];
                    float v1 = c[mt][j][rr * 2 + 1] + bias[col + 1];
                    O32[((size_t)row * Ncols + col) >> 1] = pack_bf(v0, v1);
                }
            }
        }
    }
}

// ---------------- attention: one block per (window, head), bf16 io ----------------
__global__ void attn_kernel(const float* __restrict__ mask,
                            const float* __restrict__ relt) {
    int w = blockIdx.x / NHEADS;
    int h = blockIdx.x - w * NHEADS;
    __shared__ float qs[NTOK * HD];
    __shared__ float ks[NTOK * 33];
    __shared__ float vs[NTOK * 33];
    __shared__ float sc[NTOK * 52];
    int tid = threadIdx.x, warp = tid >> 5, lane = tid & 31;
    const float scale = 0.17677669529663687f;
    const __nv_bfloat16* base = g_qkv + (size_t)w * NTOK * (3 * CH);

    for (int idx = tid; idx < NTOK * HD; idx += 256) {
        int t = idx >> 5, d = idx & 31;
        const __nv_bfloat16* p = base + t * (3 * CH) + h * HD + d;
        qs[idx]        = __bfloat162float(p[0]) * scale;
        ks[t * 33 + d] = __bfloat162float(p[CH]);
        vs[t * 33 + d] = __bfloat162float(p[2 * CH]);
    }
    __syncthreads();

    const float* mk = mask + (size_t)(w & 255) * NTOK * NTOK;
    for (int p = tid; p < NTOK * NTOK; p += 256) {
        int i = p / NTOK, j = p - i * NTOK;
        const float* qp = qs + i * HD;
        const float* kp = ks + j * 33;
        float s = 0.f;
        #pragma unroll
        for (int d = 0; d < HD; d++) s += qp[d] * kp[d];
        int ri = i / 7, ci = i - ri * 7;
        int rj = j / 7, cj = j - rj * 7;
        int bidx = (ri - rj + 6) * 13 + (ci - cj + 6);
        s += relt[bidx * NHEADS + h] + mk[p];
        sc[i * 52 + j] = s;
    }
    __syncthreads();

    // warp-parallel softmax: warp per row
    for (int i = warp; i < NTOK; i += 8) {
        float* rowp = sc + i * 52;
        float m0 = rowp[lane];
        float m1 = (lane < 17) ? rowp[lane + 32] : -1e30f;
        float mx = fmaxf(m0, m1);
        #pragma unroll
        for (int o = 16; o > 0; o >>= 1) mx = fmaxf(mx, __shfl_xor_sync(~0u, mx, o));
        float e0 = __expf(m0 - mx);
        float e1 = (lane < 17) ? __expf(m1 - mx) : 0.f;
        float sum = e0 + e1;
        #pragma unroll
        for (int o = 16; o > 0; o >>= 1) sum += __shfl_xor_sync(~0u, sum, o);
        float inv = 1.f / sum;
        rowp[lane] = e0 * inv;
        if (lane < 17) rowp[lane + 32] = e1 * inv;
    }
    __syncthreads();

    for (int p = tid; p < NTOK * HD; p += 256) {
        int i = p >> 5, d = p & 31;
        const float* sp = sc + i * 52;
        float acc = 0.f;
        #pragma unroll 7
        for (int j = 0; j < NTOK; j++) acc += sp[j] * vs[j * 33 + d];
        g_att[(size_t)(w * NTOK + i) * CH + h * HD + d] = __float2bfloat16_rn(acc);
    }
}

// ---------------- fused MLP: LN2 + fc1 + GELU + fc2 + residual ----------------
// BM=128 rows per block, hidden dim processed in 4 chunks of 96.
__global__ void __launch_bounds__(256)
mlp_fused(const float* __restrict__ xmid, const float* __restrict__ g2,
          const float* __restrict__ b2, const uint32_t* __restrict__ w1p,
          const float* __restrict__ bias1, const uint32_t* __restrict__ w2p,
          const float* __restrict__ bias2, float* __restrict__ out) {
    extern __shared__ uint32_t sm[];
    uint32_t (*P)[136]   = (uint32_t(*)[136])sm;                      // 48*136
    uint32_t (*Hs)[136]  = (uint32_t(*)[136])(sm + 48 * 136);         // 48*136
    uint32_t (*W1s)[104] = (uint32_t(*)[104])(sm + 2 * 48 * 136);     // 48*104
    uint32_t (*W2s)[104] = (uint32_t(*)[104])(sm + 2 * 48 * 136 + 48 * 104);
    float* gb = (float*)(sm + 2 * 48 * 136 + 2 * 48 * 104);           // 192

    int tid = threadIdx.x, warp = tid >> 5, lane = tid & 31;
    int g = lane >> 2, tg = lane & 3;
    int wm = (warp >> 1) * 32, wn = (warp & 1) * 48;
    int rowBase = blockIdx.x * 128;

    if (tid < 192) gb[tid] = (tid < 96) ? g2[tid] : b2[tid - 96];

    // LN2: thread = (row, half); 48 vals each
    int row = tid >> 1, half = tid & 1;
    const float4* xp = (const float4*)(xmid + (size_t)(rowBase + row) * 96 + half * 48);
    float v[48];
    float s = 0.f, ss = 0.f;
    #pragma unroll
    for (int i = 0; i < 12; i++) {
        float4 t = xp[i];
        v[4*i] = t.x; v[4*i+1] = t.y; v[4*i+2] = t.z; v[4*i+3] = t.w;
        s  += t.x + t.y + t.z + t.w;
        ss += t.x*t.x + t.y*t.y + t.z*t.z + t.w*t.w;
    }
    s  += __shfl_xor_sync(~0u, s, 1);
    ss += __shfl_xor_sync(~0u, ss, 1);
    float mean = s * (1.f / 96.f);
    float var  = ss * (1.f / 96.f) - mean * mean;
    float inv  = rsqrtf(var + 1e-5f);
    __syncthreads();   // gb visible
    #pragma unroll
    for (int q = 0; q < 24; q++) {
        int c0 = half * 48 + 2 * q;
        float y0 = (v[2*q]   - mean) * inv * gb[c0]     + gb[96 + c0];
        float y1 = (v[2*q+1] - mean) * inv * gb[c0 + 1] + gb[96 + c0 + 1];
        P[half * 24 + q][row] = pack_bf(y0, y1);
    }

    float c2[2][6][4];
    #pragma unroll
    for (int mt = 0; mt < 2; mt++)
        #pragma unroll
        for (int j = 0; j < 6; j++)
            #pragma unroll
            for (int q = 0; q < 4; q++) c2[mt][j][q] = 0.f;

    for (int ch = 0; ch < 4; ch++) {
        #pragma unroll
        for (int i = 0; i < 18; i++) {
            int idx = tid + 256 * i;
            int kp = idx / 96, n = idx - kp * 96;
            W1s[kp][n] = w1p[(size_t)kp * 384 + ch * 96 + n];
            W2s[kp][n] = w2p[(size_t)(ch * 48 + kp) * 96 + n];
        }
        __syncthreads();  // P + weights ready

        float c1[2][6][4];
        #pragma unroll
        for (int mt = 0; mt < 2; mt++)
            #pragma unroll
            for (int j = 0; j < 6; j++)
                #pragma unroll
                for (int q = 0; q < 4; q++) c1[mt][j][q] = 0.f;

        gemm_frag_96(P, W1s, wm, wn, g, tg, c1);

        // bias1 + exact GELU + pack to Hs
        #pragma unroll
        for (int mt = 0; mt < 2; mt++) {
            #pragma unroll
            for (int rr = 0; rr < 2; rr++) {
                int rloc = wm + mt * 16 + g + rr * 8;
                #pragma unroll
                for (int j = 0; j < 6; j++) {
                    int col = wn + 8 * j + 2 * tg;
                    float v0 = c1[mt][j][rr*2]     + __ldg(bias1 + ch * 96 + col);
                    float v1 = c1[mt][j][rr*2 + 1] + __ldg(bias1 + ch * 96 + col + 1);
                    v0 = 0.5f * v0 * (1.f + erff(v0 * 0.70710678118654752f));
                    v1 = 0.5f * v1 * (1.f + erff(v1 * 0.70710678118654752f));
                    Hs[(wn >> 1) + 4 * j + tg][rloc] = pack_bf(v0, v1);
                }
            }
        }
        __syncthreads();  // Hs complete

        gemm_frag_96(Hs, W2s, wm, wn, g, tg, c2);
        __syncthreads();  // done reading before next chunk overwrites
    }

    #pragma unroll
    for (int mt = 0; mt < 2; mt++) {
        #pragma unroll
        for (int rr = 0; rr < 2; rr++) {
            int rowg = rowBase + wm + mt * 16 + g + rr * 8;
            size_t base = (size_t)rowg * 96;
            #pragma unroll
            for (int j = 0; j < 6; j++) {
                int col = wn + 8 * j + 2 * tg;
                out[base + col]     = c2[mt][j][rr*2]     + bias2[col]     + xmid[base + col];
                out[base + col + 1] = c2[mt][j][rr*2 + 1] + bias2[col + 1] + xmid[base + col + 1];
            }
        }
    }
}

// ---------------- launch ----------------
extern "C" void kernel_launch(void* const* d_in, const int* in_sizes, int n_in,
                              void* d_out, int out_size) {
    const float* x     = (const float*)d_in[0];
    const float* mask  = (const float*)d_in[1];
    const float* n1g   = (const float*)d_in[2];
    const float* n1b   = (const float*)d_in[3];
    const float* qkvw  = (const float*)d_in[4];
    const float* qkvb  = (const float*)d_in[5];
    const float* relt  = (const float*)d_in[6];
    const float* projw = (const float*)d_in[7];
    const float* projb = (const float*)d_in[8];
    const float* n2g   = (const float*)d_in[9];
    const float* n2b   = (const float*)d_in[10];
    const float* fc1w  = (const float*)d_in[11];
    const float* fc1b  = (const float*)d_in[12];
    const float* fc2w  = (const float*)d_in[13];
    const float* fc2b  = (const float*)d_in[14];
    float* out = (float*)d_out;

    __nv_bfloat16 *p_xw, *p_qkv, *p_att;
    float *p_xmid;
    uint32_t *p_wqkv, *p_wproj, *p_wfc1, *p_wfc2;
    cudaGetSymbolAddress((void**)&p_xw,   g_xw);
    cudaGetSymbolAddress((void**)&p_qkv,  g_qkv);
    cudaGetSymbolAddress((void**)&p_att,  g_att);
    cudaGetSymbolAddress((void**)&p_xmid, g_xmid);
    cudaGetSymbolAddress((void**)&p_wqkv, g_wqkvp);
    cudaGetSymbolAddress((void**)&p_wproj,g_wprojp);
    cudaGetSymbolAddress((void**)&p_wfc1, g_wfc1p);
    cudaGetSymbolAddress((void**)&p_wfc2, g_wfc2p);

    const int MLP_SMEM = (2 * 48 * 136 + 2 * 48 * 104) * 4 + 192 * 4;
    cudaFuncSetAttribute(mlp_fused, cudaFuncAttributeMaxDynamicSharedMemorySize, MLP_SMEM);

    prep_weights<<<216, 256>>>(qkvw, projw, fc1w, fc2w);
    ln1_gather<<<MROWS/8, 256>>>(x, n1g, n1b);
    gemm_bf16<0><<<dim3(3, MROWS/128), 256>>>(p_xw, p_wqkv, qkvb, p_qkv, 3*CH, nullptr);
    attn_kernel<<<TOTW * NHEADS, 256>>>(mask, relt);
    gemm_bf16<3><<<dim3(1, MROWS/128), 256>>>(p_att, p_wproj, projb, p_xmid, CH, x);
    mlp_fused<<<MROWS/128, 256, MLP_SMEM>>>(p_xmid, n2g, n2b, p_wfc1, fc1b, p_wfc2, fc2b, out);
}